// round 12
// baseline (speedup 1.0000x reference)
#include <cuda_runtime.h>
#include <math.h>

#define BB 32
#define PP 24564
#define TT 20
#define CC 81

#define THRESH_HI 0.5f
#define THRESH_LO 0.4f
#define ALPHA     0.25f
#define VAR0      0.1f
#define VAR1      0.2f

#define NROWS      (BB * PP)           // 786048
#define TILE_ROWS  128                 // per block
#define TILE_FLTS  (TILE_ROWS * CC)    // 10368 floats (41472 B)
#define TILE_BYTES (TILE_FLTS * 4)
#define NTILES     (NROWS / TILE_ROWS) // 6141 (exact)
#define LBLK       256                 // 8 warps, 16 rows per warp
#define RPWARP     16
#define CHUNK_FLTS (RPWARP * CC)       // 1296 floats per warp
#define HALF_FLTS  (CHUNK_FLTS / 2)    // 648 floats (8 rows)
#define HALF_F4    (HALF_FLTS / 4)     // 162

// ---------------- device scratch (no allocations allowed) ----------------
__device__ unsigned long long g_best_prior[BB * TT]; // packed (iou_bits<<32)|(~p)
__device__ int   g_tgt[NROWS];         // packed: (tgt+1) in [0..81] low 8 | ti<<8
__device__ float g_part_l[NTILES];
__device__ float g_part_c[NTILES];
__device__ int   g_part_n[NTILES];

// ---------------- kernel 0: init ----------------
__global__ void init_kernel() {
    for (int i = threadIdx.x; i < BB * TT; i += blockDim.x)
        g_best_prior[i] = 0ull;
}

// ---- kernel 1: jaccard, 4 priors/thread; per-prior argmax over truths;
//      per-truth argmax over priors via REDUX max + ballot election -------
__global__ void match_kernel(const float* __restrict__ priors,
                             const float* __restrict__ targets) {
    __shared__ float s_t[TT][4];
    __shared__ float s_lab[TT];
    __shared__ unsigned long long s_key[TT];
    const int b    = blockIdx.y;
    const int tid  = threadIdx.x;
    const int lane = tid & 31;

    if (tid < TT) {
        const float* tb = targets + (b * TT + tid) * 5;
        s_t[tid][0] = tb[0]; s_t[tid][1] = tb[1];
        s_t[tid][2] = tb[2]; s_t[tid][3] = tb[3];
        s_lab[tid]  = tb[4];
        s_key[tid]  = 0ull;
    }
    __syncthreads();

    const int p0 = blockIdx.x * 1024 + 4 * tid;    // PP % 4 == 0 -> quads intact
    const bool ok = (p0 < PP);

    float x1[4], y1[4], x2[4], y2[4], ar[4];
    #pragma unroll
    for (int i = 0; i < 4; i++) {
        float4 pr = make_float4(0.5f, 0.5f, 0.1f, 0.1f);
        if (ok) pr = reinterpret_cast<const float4*>(priors)[p0 + i];
        x1[i] = pr.x - pr.z * 0.5f;  y1[i] = pr.y - pr.w * 0.5f;
        x2[i] = pr.x + pr.z * 0.5f;  y2[i] = pr.y + pr.w * 0.5f;
        ar[i] = pr.z * pr.w;
    }

    float bo[4] = {-1.0f, -1.0f, -1.0f, -1.0f};
    int   bt[4] = {0, 0, 0, 0};

    #pragma unroll
    for (int t = 0; t < TT; t++) {
        const float tx1 = s_t[t][0], ty1 = s_t[t][1];
        const float tx2 = s_t[t][2], ty2 = s_t[t][3];
        const float areat = (tx2 - tx1) * (ty2 - ty1);

        unsigned u[4];
        unsigned umax = 0u;
        #pragma unroll
        for (int i = 0; i < 4; i++) {
            float iw = fminf(x2[i], tx2) - fmaxf(x1[i], tx1);
            float ih = fminf(y2[i], ty2) - fmaxf(y1[i], ty1);
            iw = fmaxf(iw, 0.0f); ih = fmaxf(ih, 0.0f);
            const float inter = iw * ih;
            const float iou   = __fdividef(inter, areat + ar[i] - inter);
            if (iou > bo[i]) { bo[i] = iou; bt[i] = t; }    // first occurrence
            u[i] = ok ? __float_as_uint(iou) : 0u;          // iou >= 0
            umax = (u[i] > umax) ? u[i] : umax;
        }

        // warp argmax over 128 priors; lowest hit lane + lowest quad index
        // hold the smallest matching prior index (p grows with lane and i).
        const unsigned m   = __reduce_max_sync(0xFFFFFFFFu, umax);
        const unsigned hit = __ballot_sync(0xFFFFFFFFu, ok && umax == m);
        if (lane == (__ffs(hit) - 1)) {
            int ii = 0;
            #pragma unroll
            for (int i = 3; i >= 0; i--)
                if (u[i] == m) ii = i;
            const unsigned pmin = (unsigned)(p0 + ii);
            const unsigned long long key = (((unsigned long long)m) << 32)
                                         | (unsigned long long)(0xFFFFFFFFu - pmin);
            atomicMax(&s_key[t], key);
        }
    }

    if (ok) {
        int4 v;
        int* vp = reinterpret_cast<int*>(&v);
        #pragma unroll
        for (int i = 0; i < 4; i++) {
            int tgt = (int)s_lab[bt[i]] + 1;
            if (bo[i] < THRESH_HI) tgt = -1;
            if (bo[i] < THRESH_LO) tgt = 0;
            vp[i] = ((tgt + 1) & 0xFF) | (bt[i] << 8);
        }
        *reinterpret_cast<int4*>(g_tgt + b * PP + p0) = v;
    }
    __syncthreads();
    if (tid < TT) atomicMax(&g_best_prior[b * TT + tid], s_key[tid]);
}

// ---------------- kernel 2: force match (sequential per batch -> last-wins) ----
__global__ void force_kernel(const float* __restrict__ targets) {
    const int b = threadIdx.x;
    if (b < BB) {
        for (int t = 0; t < TT; t++) {
            unsigned long long key = g_best_prior[b * TT + t];
            unsigned p = 0xFFFFFFFFu - (unsigned)(key & 0xFFFFFFFFull);
            float lab = targets[(b * TT + t) * 5 + 4];
            g_tgt[b * PP + p] = (((int)lab + 2) & 0xFF) | (t << 8);
        }
    }
}

// ---- cp.async helpers ----
__device__ __forceinline__ void cp16(unsigned dst, const void* src) {
    asm volatile("cp.async.cg.shared.global [%0], [%1], 16;\n"
                 :: "r"(dst), "l"(src));
}
__device__ __forceinline__ void cp_commit() {
    asm volatile("cp.async.commit_group;\n");
}
template<int N>
__device__ __forceinline__ void cp_wait() {
    asm volatile("cp.async.wait_group %0;\n" :: "n"(N));
}

// per-half compute: 8 rows, 4 threads/row; q==0 lane accumulates the losses
__device__ __forceinline__ void process_half(
    const float* __restrict__ half_base,    // smem, 8 rows x 81
    int pk, int myrow, int r4, int q, int qoff,
    const float* __restrict__ loc,
    const float* __restrict__ priors,
    const float* __restrict__ targets,
    float& fl, float& ll, int& np)
{
    const float* my = half_base + r4 * CC + qoff;
    float psum = 0.0f;
    #pragma unroll
    for (int k = 0; k < 20; k++)
        psum += __expf(my[k]);
    if (q == 0) psum += __expf(my[20]);
    psum += __shfl_xor_sync(0xFFFFFFFFu, psum, 1);
    psum += __shfl_xor_sync(0xFFFFFFFFu, psum, 2);   // full row sum in quad

    if (q == 0) {
        const int tg = (pk & 0xFF) - 1;       // -1, 0, or 1..80
        if (tg >= 0) {                        // valid -> focal loss
            const float xt    = half_base[r4 * CC + (tg < 0 ? 0 : tg)];
            const float lse   = __logf(psum);
            const float logpt = xt - lse;
            const float pt    = __expf(logpt);
            const float at    = (tg > 0) ? ALPHA : (1.0f - ALPHA);
            const float om    = 1.0f - pt;
            fl += -at * om * om * logpt;
        }
        if (tg > 0) {                         // positive (rare) -> smooth-L1
            np++;
            const int b  = myrow / PP;
            const int p  = myrow - b * PP;
            const int ti = (pk >> 8) & 0xFF;
            const float* tb = targets + (b * TT + ti) * 5;
            const float tx1 = tb[0], ty1 = tb[1], tx2 = tb[2], ty2 = tb[3];
            const float4 pr = reinterpret_cast<const float4*>(priors)[p];

            const float gcx = ((tx1 + tx2) * 0.5f - pr.x) / (VAR0 * pr.z);
            const float gcy = ((ty1 + ty2) * 0.5f - pr.y) / (VAR0 * pr.w);
            const float gw  = __logf((tx2 - tx1) / pr.z) / VAR1;
            const float gh  = __logf((ty2 - ty1) / pr.w) / VAR1;

            const float4 ld = reinterpret_cast<const float4*>(loc)[myrow];
            const float d0 = ld.x - gcx, d1 = ld.y - gcy;
            const float d2 = ld.z - gw,  d3 = ld.w - gh;
            float ad;
            ad = fabsf(d0); ll += (ad < 1.0f) ? 0.5f * d0 * d0 : ad - 0.5f;
            ad = fabsf(d1); ll += (ad < 1.0f) ? 0.5f * d1 * d1 : ad - 0.5f;
            ad = fabsf(d2); ll += (ad < 1.0f) ? 0.5f * d2 * d2 : ad - 0.5f;
            ad = fabsf(d3); ll += (ad < 1.0f) ? 0.5f * d3 * d3 : ad - 0.5f;
        }
    }
}

// ---- kernel 3: warp-autonomous loss, split-commit staging (R9 + overlap) ----
// Each warp stages its 16 rows as TWO cp.async groups; computes rows 0-7
// under wait<1> while rows 8-15 are still in flight. No block barriers in
// the hot path. Dynamic smem (16B-aligned; scaffold identical to R9).
__global__ void __launch_bounds__(LBLK, 5)
loss_kernel(const float* __restrict__ loc,
            const float* __restrict__ conf,
            const float* __restrict__ priors,
            const float* __restrict__ targets) {
    extern __shared__ float tile[];              // TILE_FLTS floats
    __shared__ float s_fl[LBLK / 32];
    __shared__ float s_ll[LBLK / 32];
    __shared__ int   s_np[LBLK / 32];

    const int tid  = threadIdx.x;
    const int lane = tid & 31;
    const int wid  = tid >> 5;
    const int wrow0 = blockIdx.x * TILE_ROWS + wid * RPWARP;   // warp's 16 rows

    float* wbuf = tile + wid * CHUNK_FLTS;
    const unsigned wsh = (unsigned)__cvta_generic_to_shared(wbuf);

    // stage rows 0..7, then rows 8..15, as separate commit groups
    {
        const char* src = (const char*)conf + (size_t)wrow0 * CC * 4;
        #pragma unroll
        for (int i = lane; i < HALF_F4; i += 32)
            cp16(wsh + i * 16, src + i * 16);
        cp_commit();
        #pragma unroll
        for (int i = lane; i < HALF_F4; i += 32)
            cp16(wsh + HALF_FLTS * 4 + i * 16, src + HALF_FLTS * 4 + i * 16);
        cp_commit();
    }

    const int r4 = lane >> 2;                     // 0..7 (row within half)
    const int q  = lane & 3;                      // quarter of row
    const int qoff = (q == 0) ? 0 : (20 * q + 1); // {0,21,41,61}
    const int pkA = g_tgt[wrow0 + r4];            // overlap the waits
    const int pkB = g_tgt[wrow0 + 8 + r4];

    float fl = 0.0f, ll = 0.0f;
    int   np = 0;

    cp_wait<1>();                                 // half A landed; B in flight
    __syncwarp();
    process_half(wbuf, pkA, wrow0 + r4, r4, q, qoff,
                 loc, priors, targets, fl, ll, np);

    cp_wait<0>();                                 // half B landed
    __syncwarp();
    process_half(wbuf + HALF_FLTS, pkB, wrow0 + 8 + r4, r4, q, qoff,
                 loc, priors, targets, fl, ll, np);

    // warp butterfly, then one barrier for the block total
    #pragma unroll
    for (int off = 16; off > 0; off >>= 1) {
        fl += __shfl_xor_sync(0xFFFFFFFFu, fl, off);
        ll += __shfl_xor_sync(0xFFFFFFFFu, ll, off);
        np += __shfl_xor_sync(0xFFFFFFFFu, np, off);
    }
    if (lane == 0) { s_fl[wid] = fl; s_ll[wid] = ll; s_np[wid] = np; }
    __syncthreads();
    if (tid == 0) {
        float tc = 0.0f, tl = 0.0f; int tn = 0;
        #pragma unroll
        for (int i = 0; i < LBLK / 32; i++) { tc += s_fl[i]; tl += s_ll[i]; tn += s_np[i]; }
        g_part_c[blockIdx.x] = tc;
        g_part_l[blockIdx.x] = tl;
        g_part_n[blockIdx.x] = tn;
    }
}

// ---------------- kernel 4: deterministic final reduction ----------------
__global__ void final_kernel(float* __restrict__ out) {
    __shared__ double s_l[1024];
    __shared__ double s_c[1024];
    __shared__ int    s_n[1024];
    const int tid = threadIdx.x;
    double tl = 0.0, tc = 0.0; int tn = 0;
    for (int i = tid; i < NTILES; i += 1024) {
        tl += (double)g_part_l[i];
        tc += (double)g_part_c[i];
        tn += g_part_n[i];
    }
    s_l[tid] = tl; s_c[tid] = tc; s_n[tid] = tn;
    __syncthreads();
    for (int off = 512; off > 0; off >>= 1) {
        if (tid < off) {
            s_l[tid] += s_l[tid + off];
            s_c[tid] += s_c[tid + off];
            s_n[tid] += s_n[tid + off];
        }
        __syncthreads();
    }
    if (tid == 0) {
        const double n = (double)s_n[0];
        out[0] = (float)(s_l[0] / n);
        out[1] = (float)(s_c[0] / n);
    }
}

// ---------------- launch ----------------
extern "C" void kernel_launch(void* const* d_in, const int* in_sizes, int n_in,
                              void* d_out, int out_size) {
    const float* loc     = (const float*)d_in[0];   // (B,P,4)
    const float* conf    = (const float*)d_in[1];   // (B,P,81)
    const float* priors  = (const float*)d_in[2];   // (P,4)
    const float* targets = (const float*)d_in[3];   // (B,T,5)
    float* out = (float*)d_out;

    cudaFuncSetAttribute(loss_kernel,
                         cudaFuncAttributeMaxDynamicSharedMemorySize,
                         TILE_BYTES);

    init_kernel<<<1, 256>>>();

    dim3 g1((PP + 1023) / 1024, BB);
    match_kernel<<<g1, 256>>>(priors, targets);

    force_kernel<<<1, 32>>>(targets);

    loss_kernel<<<NTILES, LBLK, TILE_BYTES>>>(loc, conf, priors, targets);

    final_kernel<<<1, 1024>>>(out);
}